// round 6
// baseline (speedup 1.0000x reference)
#include <cuda_runtime.h>
#include <cuda_bf16.h>
#include <cstdint>

#define D      150
#define Dp     160
#define NTOT   25600     // Dp*Dp, n = j*160 + i
#define BZ     256
#define DIN    1024

// ---------------- scratch (__device__ globals; zero-init at load; pads never
// written -> stay zero -> no predication anywhere) -------------------------
__device__ __align__(16) float g_emb[3][BZ][Dp];
__device__ __align__(16) __nv_bfloat16 g_eh[3][BZ][Dp];      // emb hi image
__device__ __align__(16) __nv_bfloat16 g_el[3][BZ][Dp];      // emb lo image
__device__ __align__(16) __nv_bfloat16 g_tbh[6][NTOT][Dp];   // T image [q][n][k] hi
__device__ __align__(16) __nv_bfloat16 g_tbl[6][NTOT][Dp];   // lo
__device__ __align__(16) __nv_bfloat16 g_wbh[6][BZ][Dp][Dp]; // w image [q][bz][j][i] hi
__device__ __align__(16) __nv_bfloat16 g_wbl[6][BZ][Dp][Dp]; // lo

// q0 span_psh: X=sh Y=st Z=p (no sym)  q1 span_pst: X=sh Y=st Z=p (sym)
// q2 ph_sib: X=sh Y=sh Z=p   q3 pt_sib: X=st Y=st Z=p
// q4 ph_cop: X=p Y=p Z=sh    q5 pt_cop: X=p Y=p Z=st  (q4,q5 permuted out)
__constant__ int c_ZI[6] = {2,2,2,2,0,1};
__constant__ int c_XI[6] = {0,0,0,1,2,2};
__constant__ int c_YI[6] = {1,1,0,1,2,2};

// ---------------- low-level helpers ----------------------------------------
__device__ __forceinline__ uint32_t smem_u32(const void* p){
    uint32_t a;
    asm("{ .reg .u64 t; cvta.to.shared.u64 t, %1; cvt.u32.u64 %0, t; }" : "=r"(a) : "l"(p));
    return a;
}
__device__ __forceinline__ void split_pack(float a, float b, uint32_t& h, uint32_t& l){
    __nv_bfloat16 ah = __float2bfloat16(a), bh = __float2bfloat16(b);
    __nv_bfloat16 al = __float2bfloat16(a - __bfloat162float(ah));
    __nv_bfloat16 bl = __float2bfloat16(b - __bfloat162float(bh));
    h = (uint32_t)__bfloat16_as_ushort(ah) | ((uint32_t)__bfloat16_as_ushort(bh) << 16);
    l = (uint32_t)__bfloat16_as_ushort(al) | ((uint32_t)__bfloat16_as_ushort(bl) << 16);
}
__device__ __forceinline__ void mma16816(float* c, const uint32_t* a, uint32_t b0, uint32_t b1){
    asm volatile("mma.sync.aligned.m16n8k16.row.col.f32.bf16.bf16.f32 "
        "{%0,%1,%2,%3}, {%4,%5,%6,%7}, {%8,%9}, {%0,%1,%2,%3};"
        : "+f"(c[0]), "+f"(c[1]), "+f"(c[2]), "+f"(c[3])
        : "r"(a[0]), "r"(a[1]), "r"(a[2]), "r"(a[3]), "r"(b0), "r"(b1));
}
__device__ __forceinline__ void ldsm4(uint32_t* r, uint32_t a){
    asm volatile("ldmatrix.sync.aligned.m8n8.x4.shared.b16 {%0,%1,%2,%3}, [%4];"
        : "=r"(r[0]), "=r"(r[1]), "=r"(r[2]), "=r"(r[3]) : "r"(a));
}
__device__ __forceinline__ void cpa16(uint32_t s, const void* g){
    asm volatile("cp.async.cg.shared.global [%0], [%1], 16;" :: "r"(s), "l"(g));
}
#define CP_COMMIT() asm volatile("cp.async.commit_group;" ::: "memory")
#define CP_WAIT1()  asm volatile("cp.async.wait_group 1;" ::: "memory")
#define CP_WAIT0()  asm volatile("cp.async.wait_group 0;" ::: "memory")

// k16-chunk layout: 32B rows, 2x16B units; XOR swizzle (conflict-free ldsm)
__device__ __forceinline__ uint32_t swz(int row, int u){
    return (uint32_t)(row * 32 + (((u ^ (row >> 2)) & 1) << 4));
}
__device__ __forceinline__ uint32_t lds_addr(uint32_t base, int r0, int ln){
    int g = ln >> 3;
    int row = r0 + ((g & 1) << 3) + (ln & 7);
    return base + swz(row, g >> 1);
}

// 320B-row image layout (v, Y): 20x16B units per row, XOR over (row>>1)&3
__device__ __forceinline__ uint32_t voff(int row, int j){
    return (uint32_t)(row * 320 + 16 * ((j >> 3) ^ ((row >> 1) & 3)) + (j & 7) * 2);
}
__device__ __forceinline__ uint32_t vuoff(int row, int u){
    return (uint32_t)(row * 320 + 16 * (u ^ ((row >> 1) & 3)));
}
__device__ __forceinline__ uint32_t ldsV(uint32_t base, int r0, int ln, int u0){
    int g = ln >> 3;
    int row = r0 + ((g & 1) << 3) + (ln & 7);
    return base + vuoff(row, u0 + (g >> 1));
}

// ILP-4 split-major 12-MMA block: 4 targets x {hh, hl, lh}
#define MMA_BLK(t00, t01, t10, t11, ah, al, bh, bl) do { \
    mma16816(t00, ah[0], bh[0], bh[2]); \
    mma16816(t01, ah[0], bh[1], bh[3]); \
    mma16816(t10, ah[1], bh[0], bh[2]); \
    mma16816(t11, ah[1], bh[1], bh[3]); \
    mma16816(t00, ah[0], bl[0], bl[2]); \
    mma16816(t01, ah[0], bl[1], bl[3]); \
    mma16816(t10, ah[1], bl[0], bl[2]); \
    mma16816(t11, ah[1], bl[1], bl[3]); \
    mma16816(t00, al[0], bh[0], bh[2]); \
    mma16816(t01, al[0], bh[1], bh[3]); \
    mma16816(t10, al[1], bh[0], bh[2]); \
    mma16816(t11, al[1], bh[1], bh[3]); \
} while(0)

// ---------------- MLP -------------------------------------------------------
__global__ void k_mlp(const float* __restrict__ x,
                      const float* __restrict__ W0, const float* __restrict__ b0,
                      const float* __restrict__ W1, const float* __restrict__ b1,
                      const float* __restrict__ W2, const float* __restrict__ b2)
{
    int row = blockIdx.x, e = blockIdx.y;
    const float* W  = (e == 0) ? W0 : (e == 1) ? W1 : W2;
    const float* bb = (e == 0) ? b0 : (e == 1) ? b1 : b2;
    __shared__ float xs[DIN];
    int tid = threadIdx.x;
    for (int k = tid; k < DIN; k += 160) xs[k] = x[row * DIN + k];
    __syncthreads();
    if (tid < D) {
        float acc = bb[tid];
        #pragma unroll 8
        for (int k = 0; k < DIN; ++k) acc += xs[k] * W[k * D + tid];
        g_emb[e][row][tid] = (acc >= 0.f) ? acc : 0.1f * acc;
    }
}

// ---------------- emb -> split bf16 images ---------------------------------
__global__ void k_embimg()
{
    int idx = blockIdx.x * 256 + threadIdx.x;      // 3*256*80
    if (idx >= 3 * 256 * 80) return;
    int e = idx / 20480, rem = idx % 20480;
    int row = rem / 80, kp = rem % 80;
    uint32_t h, l;
    split_pack(g_emb[e][row][2*kp], g_emb[e][row][2*kp+1], h, l);
    *(uint32_t*)&g_eh[e][row][2*kp] = h;
    *(uint32_t*)&g_el[e][row][2*kp] = l;
}

// ---------------- T[i][k][j] -> TB[q][(j*160+i)][k] hi/lo -------------------
__global__ void k_timg(const float* __restrict__ T0, const float* __restrict__ T1,
                       const float* __restrict__ T2, const float* __restrict__ T3,
                       const float* __restrict__ T4, const float* __restrict__ T5)
{
    int q = blockIdx.z, i = blockIdx.y, j0 = blockIdx.x * 32;
    const float* T = (q==0)?T0:(q==1)?T1:(q==2)?T2:(q==3)?T3:(q==4)?T4:T5;
    __shared__ float ts[32][152];
    int tid = threadIdx.x;
    for (int t = tid; t < 150 * 32; t += 256) {
        int k = t >> 5, j = t & 31;
        if (j0 + j < D) ts[j][k] = T[(i * D + k) * D + j0 + j];
    }
    __syncthreads();
    for (int t = tid; t < 32 * 75; t += 256) {
        int j = t / 75, kp = t % 75;
        if (j0 + j < D) {
            uint32_t h, l;
            split_pack(ts[j][2*kp], ts[j][2*kp+1], h, l);
            int n = (j0 + j) * Dp + i;
            *(uint32_t*)&g_tbh[q][n][2*kp] = h;
            *(uint32_t*)&g_tbl[q][n][2*kp] = l;
        }
    }
}

// ---------------- stage A: w = Z . TB^T, epilogue -> wB images ---------------
// M=256, N=25600, K=160.  Tile 128x128, warp tile 32x64 (4m x 2n warps).
__device__ __forceinline__ void prefA(uint32_t sb, int buf, int k0, int tid,
    const __nv_bfloat16* Zh, const __nv_bfloat16* Zl,
    const __nv_bfloat16* Bh, const __nv_bfloat16* Bl, int m0, int n0)
{
    #pragma unroll
    for (int t3 = 0; t3 < 4; ++t3) {
        int t = tid + t3 * 256;
        int arr = t >> 8, rr = (t >> 1) & 127, u = t & 1;
        uint32_t dst = sb + buf * 16384 + arr * 4096 + swz(rr, u);
        const __nv_bfloat16* g;
        if (arr == 0)      g = Zh + (size_t)(m0 + rr) * Dp + k0 + u * 8;
        else if (arr == 1) g = Zl + (size_t)(m0 + rr) * Dp + k0 + u * 8;
        else if (arr == 2) g = Bh + (size_t)(n0 + rr) * Dp + k0 + u * 8;
        else               g = Bl + (size_t)(n0 + rr) * Dp + k0 + u * 8;
        cpa16(dst, g);
    }
    CP_COMMIT();
}

__global__ void __launch_bounds__(256, 2) k_stageA()
{
    int q = blockIdx.z, m0 = blockIdx.y * 128, n0 = blockIdx.x * 128;
    int tid = threadIdx.x, w = tid >> 5, ln = tid & 31;
    int wm = w & 3, wn = w >> 2;
    __shared__ __align__(16) unsigned char smb[2][16384];
    uint32_t sb = smem_u32(smb);
    int zi = c_ZI[q];
    const __nv_bfloat16 *Zh = &g_eh[zi][0][0], *Zl = &g_el[zi][0][0];
    const __nv_bfloat16 *Bh = &g_tbh[q][0][0], *Bl = &g_tbl[q][0][0];

    float acc[2][8][4];
    #pragma unroll
    for (int a = 0; a < 2; ++a)
        #pragma unroll
        for (int b = 0; b < 8; ++b)
            #pragma unroll
            for (int c = 0; c < 4; ++c) acc[a][b][c] = 0.f;

    prefA(sb, 0, 0, tid, Zh, Zl, Bh, Bl, m0, n0);
    for (int ks = 0; ks < 10; ++ks) {
        if (ks < 9) { prefA(sb, (ks + 1) & 1, (ks + 1) * 16, tid, Zh, Zl, Bh, Bl, m0, n0); CP_WAIT1(); }
        else CP_WAIT0();
        __syncthreads();
        uint32_t base = sb + (ks & 1) * 16384;
        uint32_t ah[2][4], al[2][4];
        #pragma unroll
        for (int mt = 0; mt < 2; ++mt) {
            ldsm4(ah[mt], lds_addr(base,        wm * 32 + mt * 16, ln));
            ldsm4(al[mt], lds_addr(base + 4096, wm * 32 + mt * 16, ln));
        }
        #pragma unroll
        for (int p = 0; p < 4; ++p) {
            uint32_t bh[4], bl[4];
            ldsm4(bh, lds_addr(base + 8192,  wn * 64 + p * 16, ln));
            ldsm4(bl, lds_addr(base + 12288, wn * 64 + p * 16, ln));
            MMA_BLK(acc[0][2*p], acc[0][2*p+1], acc[1][2*p], acc[1][2*p+1], ah, al, bh, bl);
        }
        __syncthreads();
    }

    // epilogue: c-frag cols = flattened n; store wB pairs (n even)
    __nv_bfloat16* WH = &g_wbh[0][0][0][0];
    __nv_bfloat16* WL = &g_wbl[0][0][0][0];
    int yb = 2 * (ln & 3);
    #pragma unroll
    for (int mt = 0; mt < 2; ++mt) {
        int mA = m0 + wm * 32 + mt * 16 + (ln >> 2);
        #pragma unroll
        for (int nt = 0; nt < 8; ++nt) {
            int n = n0 + wn * 64 + nt * 8 + yb;
            size_t off0 = ((size_t)(q * BZ + mA)) * 25600 + n;
            size_t off1 = off0 + (size_t)8 * 25600;
            uint32_t h, l;
            split_pack(acc[mt][nt][0], acc[mt][nt][1], h, l);
            *(uint32_t*)(WH + off0) = h; *(uint32_t*)(WL + off0) = l;
            split_pack(acc[mt][nt][2], acc[mt][nt][3], h, l);
            *(uint32_t*)(WH + off1) = h; *(uint32_t*)(WL + off1) = l;
        }
    }
}

// ---------------- fused B+C per (q,bz) --------------------------------------
// B: v[x][j] = sum_i X[x][i] wB[j][i]   (128x160x160), warp tile 32x80
//    epilogue: v -> split-bf16 smem images (320B-row swizzled)
// C: s[x][y] = sum_j v[x][j] Y[y][j]    (128x128x160), warp tile 32x64,
//    A and B both straight from smem images (no staging, no syncs)
// dyn smem: [0,36864) B-chunk bufs -> reused as Y images [0,81920)
//           [81920,163840) v images
__device__ __forceinline__ void prefB(uint32_t sb, int buf, int k0, int tid,
    const __nv_bfloat16* Xh, const __nv_bfloat16* Xl,
    const __nv_bfloat16* Wh, const __nv_bfloat16* Wl)
{
    for (int t = tid; t < 1152; t += 256) {
        uint32_t dst; const __nv_bfloat16* g;
        if (t < 512) {
            int img = t >> 8, rr = (t >> 1) & 127, u = t & 1;
            dst = sb + buf * 18432 + img * 4096 + swz(rr, u);
            g = (img ? Xl : Xh) + (size_t)rr * Dp + k0 + u * 8;
        } else {
            int t2 = t - 512;                              // 0..639
            int img = t2 / 320, r2 = t2 - img * 320;       // 2 imgs x 160 rows x 2 units
            int rr = r2 >> 1, u = r2 & 1;
            dst = sb + buf * 18432 + 8192 + img * 5120 + swz(rr, u);
            g = (img ? Wl : Wh) + (size_t)rr * Dp + k0 + u * 8;
        }
        cpa16(dst, g);
    }
    CP_COMMIT();
}
__device__ __forceinline__ void sym_store(float* o, int x, int y, float v, int sx, int sy){
    if (x <= y) {
        o[(size_t)x * sx + (size_t)y * sy] = v;
        if (x < y) o[(size_t)y * sx + (size_t)x * sy] = v;
    }
}

__global__ void __launch_bounds__(256, 1) k_fusedBC(float* __restrict__ out)
{
    extern __shared__ __align__(16) unsigned char dynsm[];
    uint32_t sb = smem_u32(dynsm);
    int q = blockIdx.y, bz = blockIdx.x, b = bz >> 7, z = bz & 127;
    int tid = threadIdx.x, w = tid >> 5, ln = tid & 31;
    int wm = w & 3, wn = w >> 2;

    const __nv_bfloat16 *Xh = &g_eh[c_XI[q]][b*128][0], *Xl = &g_el[c_XI[q]][b*128][0];
    const __nv_bfloat16 *Wh = &g_wbh[q][bz][0][0],      *Wl = &g_wbl[q][bz][0][0];
    const __nv_bfloat16 *Yh = &g_eh[c_YI[q]][b*128][0], *Yl = &g_el[c_YI[q]][b*128][0];

    // ---- stage B (warp tile 32x80; warps 4m x 2n)
    float accB[2][10][4];
    #pragma unroll
    for (int mt = 0; mt < 2; ++mt)
        #pragma unroll
        for (int i = 0; i < 10; ++i)
            #pragma unroll
            for (int c = 0; c < 4; ++c) accB[mt][i][c] = 0.f;

    prefB(sb, 0, 0, tid, Xh, Xl, Wh, Wl);
    for (int ks = 0; ks < 10; ++ks) {
        if (ks < 9) { prefB(sb, (ks + 1) & 1, (ks + 1) * 16, tid, Xh, Xl, Wh, Wl); CP_WAIT1(); }
        else CP_WAIT0();
        __syncthreads();
        uint32_t base = sb + (ks & 1) * 18432;
        uint32_t ah[2][4], al[2][4];
        #pragma unroll
        for (int mt = 0; mt < 2; ++mt) {
            ldsm4(ah[mt], lds_addr(base,        wm * 32 + mt * 16, ln));
            ldsm4(al[mt], lds_addr(base + 4096, wm * 32 + mt * 16, ln));
        }
        #pragma unroll
        for (int p = 0; p < 5; ++p) {
            uint32_t bh[4], bl[4];
            ldsm4(bh, lds_addr(base + 8192,  wn * 80 + p * 16, ln));
            ldsm4(bl, lds_addr(base + 13312, wn * 80 + p * 16, ln));
            MMA_BLK(accB[0][2*p], accB[0][2*p+1], accB[1][2*p], accB[1][2*p+1], ah, al, bh, bl);
        }
        __syncthreads();
    }

    // ---- Y prefetch into [0,81920) (bufs dead), overlapped with v writes
    for (int t = tid; t < 5120; t += 256) {
        int img = t / 2560, r2 = t % 2560;
        int r = r2 / 20, u = r2 % 20;
        uint32_t dst = sb + img * 40960 + vuoff(r, u);
        const __nv_bfloat16* g = (img ? Yl : Yh) + (size_t)r * Dp + u * 8;
        cpa16(dst, g);
    }
    CP_COMMIT();

    // ---- v -> split-bf16 smem images at [81920,163840)
    #pragma unroll
    for (int mt = 0; mt < 2; ++mt) {
        #pragma unroll
        for (int n8 = 0; n8 < 10; ++n8) {
            int j  = wn * 80 + n8 * 8 + 2 * (ln & 3);
            int x1 = wm * 32 + mt * 16 + (ln >> 2);
            uint32_t h, l;
            split_pack(accB[mt][n8][0], accB[mt][n8][1], h, l);
            *(uint32_t*)(dynsm + 81920  + voff(x1, j)) = h;
            *(uint32_t*)(dynsm + 122880 + voff(x1, j)) = l;
            split_pack(accB[mt][n8][2], accB[mt][n8][3], h, l);
            *(uint32_t*)(dynsm + 81920  + voff(x1 + 8, j)) = h;
            *(uint32_t*)(dynsm + 122880 + voff(x1 + 8, j)) = l;
        }
    }
    CP_WAIT0();
    __syncthreads();

    // ---- stage C (warp tile 32x64; pure ldsm+mma from images, no syncs)
    float accC[2][8][4];
    #pragma unroll
    for (int mt = 0; mt < 2; ++mt)
        #pragma unroll
        for (int i = 0; i < 8; ++i)
            #pragma unroll
            for (int c = 0; c < 4; ++c) accC[mt][i][c] = 0.f;

    #pragma unroll
    for (int kk = 0; kk < 10; ++kk) {
        int u0 = kk * 2;
        uint32_t ah[2][4], al[2][4];
        #pragma unroll
        for (int mt = 0; mt < 2; ++mt) {
            ldsm4(ah[mt], ldsV(sb + 81920,  wm * 32 + mt * 16, ln, u0));
            ldsm4(al[mt], ldsV(sb + 122880, wm * 32 + mt * 16, ln, u0));
        }
        #pragma unroll
        for (int p = 0; p < 4; ++p) {
            uint32_t bh[4], bl[4];
            ldsm4(bh, ldsV(sb,         wn * 64 + p * 16, ln, u0));
            ldsm4(bl, ldsV(sb + 40960, wn * 64 + p * 16, ln, u0));
            MMA_BLK(accC[0][2*p], accC[0][2*p+1], accC[1][2*p], accC[1][2*p+1], ah, al, bh, bl);
        }
    }

    // ---- epilogue: triu_sym dual-write; q>=4 permuted strides
    int yb = 2 * (ln & 3);
    if (q == 0) {
        float* o = out + (size_t)bz * 16384;
        #pragma unroll
        for (int mt = 0; mt < 2; ++mt) {
            int x0 = wm * 32 + mt * 16 + (ln >> 2);
            #pragma unroll
            for (int nt = 0; nt < 8; ++nt) {
                int y = wn * 64 + nt * 8 + yb;
                float2 v0 = {accC[mt][nt][0], accC[mt][nt][1]};
                float2 v1 = {accC[mt][nt][2], accC[mt][nt][3]};
                *(float2*)(o + (size_t)x0 * 128 + y)       = v0;
                *(float2*)(o + (size_t)(x0 + 8) * 128 + y) = v1;
            }
        }
    } else {
        float* o; int sx, sy;
        if (q < 4) { o = out + (size_t)q * 4194304 + (size_t)bz * 16384;      sx = 128;   sy = 1;   }
        else       { o = out + (size_t)q * 4194304 + (size_t)b * 2097152 + z; sx = 16384; sy = 128; }
        #pragma unroll
        for (int mt = 0; mt < 2; ++mt) {
            int x0 = wm * 32 + mt * 16 + (ln >> 2);
            #pragma unroll
            for (int nt = 0; nt < 8; ++nt) {
                int y = wn * 64 + nt * 8 + yb;
                sym_store(o, x0,     y,     accC[mt][nt][0], sx, sy);
                sym_store(o, x0,     y + 1, accC[mt][nt][1], sx, sy);
                sym_store(o, x0 + 8, y,     accC[mt][nt][2], sx, sy);
                sym_store(o, x0 + 8, y + 1, accC[mt][nt][3], sx, sy);
            }
        }
    }
}

// ---------------------------------------------------------------------------
extern "C" void kernel_launch(void* const* d_in, const int* in_sizes, int n_in,
                              void* d_out, int out_size)
{
    const float* x      = (const float*)d_in[0];
    const float* W_sh   = (const float*)d_in[1];
    const float* b_sh   = (const float*)d_in[2];
    const float* W_st   = (const float*)d_in[3];
    const float* b_st   = (const float*)d_in[4];
    const float* W_p    = (const float*)d_in[5];
    const float* b_p    = (const float*)d_in[6];
    const float* T_pt   = (const float*)d_in[7];
    const float* T_ph   = (const float*)d_in[8];
    const float* T_phsib= (const float*)d_in[9];
    const float* T_ptsib= (const float*)d_in[10];
    const float* T_phcop= (const float*)d_in[11];
    const float* T_ptcop= (const float*)d_in[12];

    static bool attr_done = false;
    if (!attr_done) {
        cudaFuncSetAttribute(k_fusedBC, cudaFuncAttributeMaxDynamicSharedMemorySize, 163840);
        attr_done = true;
    }

    k_mlp   <<<dim3(BZ, 3), 160>>>(x, W_sh, b_sh, W_st, b_st, W_p, b_p);
    k_embimg<<<240, 256>>>();
    // q order: 0=T_ph 1=T_pt 2=T_phsib 3=T_ptsib 4=T_phcop 5=T_ptcop
    k_timg  <<<dim3(5, D, 6), 256>>>(T_ph, T_pt, T_phsib, T_ptsib, T_phcop, T_ptcop);
    k_stageA<<<dim3(200, 2, 6), 256>>>();
    k_fusedBC<<<dim3(BZ, 6), 256, 163840>>>((float*)d_out);
}

// round 7
// speedup vs baseline: 1.0507x; 1.0507x over previous
#include <cuda_runtime.h>
#include <cuda_bf16.h>
#include <cstdint>

#define D      150
#define Dp     160
#define NTOT   25600     // Dp*Dp, n = j*160 + i
#define BZ     256
#define DIN    1024

// ---------------- scratch (__device__ globals; zero-init; pads never written)
__device__ __align__(16) float g_emb[3][BZ][Dp];
__device__ __align__(16) __nv_bfloat16 g_eh[3][BZ][Dp];      // emb hi image
__device__ __align__(16) __nv_bfloat16 g_el[3][BZ][Dp];      // emb lo image
__device__ __align__(16) __nv_bfloat16 g_tbh[6][NTOT][Dp];   // T image [q][n][k] hi
__device__ __align__(16) __nv_bfloat16 g_tbl[6][NTOT][Dp];   // lo
__device__ __align__(16) __nv_bfloat16 g_wbh[6][BZ][Dp][Dp]; // w image [q][bz][j][i] hi
__device__ __align__(16) __nv_bfloat16 g_wbl[6][BZ][Dp][Dp]; // lo
__device__ __align__(16) float g_cp[4][128][128][128];       // [t*2+b][z][x][y] co-parent staging

// q0 span_psh: X=sh Y=st Z=p (no sym)  q1 span_pst (sym)
// q2 ph_sib: X=sh Y=sh Z=p   q3 pt_sib: X=st Y=st Z=p
// q4 ph_cop: X=p Y=p Z=sh    q5 pt_cop: X=p Y=p Z=st  (q4,q5 permuted out)
__constant__ int c_ZI[6] = {2,2,2,2,0,1};
__constant__ int c_XI[6] = {0,0,0,1,2,2};
__constant__ int c_YI[6] = {1,1,0,1,2,2};

// ---------------- low-level helpers ----------------------------------------
__device__ __forceinline__ uint32_t smem_u32(const void* p){
    uint32_t a;
    asm("{ .reg .u64 t; cvta.to.shared.u64 t, %1; cvt.u32.u64 %0, t; }" : "=r"(a) : "l"(p));
    return a;
}
__device__ __forceinline__ void split_pack(float a, float b, uint32_t& h, uint32_t& l){
    __nv_bfloat16 ah = __float2bfloat16(a), bh = __float2bfloat16(b);
    __nv_bfloat16 al = __float2bfloat16(a - __bfloat162float(ah));
    __nv_bfloat16 bl = __float2bfloat16(b - __bfloat162float(bh));
    h = (uint32_t)__bfloat16_as_ushort(ah) | ((uint32_t)__bfloat16_as_ushort(bh) << 16);
    l = (uint32_t)__bfloat16_as_ushort(al) | ((uint32_t)__bfloat16_as_ushort(bl) << 16);
}
__device__ __forceinline__ void mma16816(float* c, const uint32_t* a, uint32_t b0, uint32_t b1){
    asm volatile("mma.sync.aligned.m16n8k16.row.col.f32.bf16.bf16.f32 "
        "{%0,%1,%2,%3}, {%4,%5,%6,%7}, {%8,%9}, {%0,%1,%2,%3};"
        : "+f"(c[0]), "+f"(c[1]), "+f"(c[2]), "+f"(c[3])
        : "r"(a[0]), "r"(a[1]), "r"(a[2]), "r"(a[3]), "r"(b0), "r"(b1));
}
__device__ __forceinline__ void ldsm4(uint32_t* r, uint32_t a){
    asm volatile("ldmatrix.sync.aligned.m8n8.x4.shared.b16 {%0,%1,%2,%3}, [%4];"
        : "=r"(r[0]), "=r"(r[1]), "=r"(r[2]), "=r"(r[3]) : "r"(a));
}
__device__ __forceinline__ void cpa16(uint32_t s, const void* g){
    asm volatile("cp.async.cg.shared.global [%0], [%1], 16;" :: "r"(s), "l"(g));
}
#define CP_COMMIT() asm volatile("cp.async.commit_group;" ::: "memory")
#define CP_WAIT2()  asm volatile("cp.async.wait_group 2;" ::: "memory")
#define CP_WAIT0()  asm volatile("cp.async.wait_group 0;" ::: "memory")

// k16-chunk layout: 32B rows, 2x16B units; XOR swizzle (conflict-free ldsm)
__device__ __forceinline__ uint32_t swz(int row, int u){
    return (uint32_t)(row * 32 + (((u ^ (row >> 2)) & 1) << 4));
}
__device__ __forceinline__ uint32_t lds_addr(uint32_t base, int r0, int ln){
    int g = ln >> 3;
    int row = r0 + ((g & 1) << 3) + (ln & 7);
    return base + swz(row, g >> 1);
}
// 320B-row image layout (v, Y)
__device__ __forceinline__ uint32_t voff(int row, int j){
    return (uint32_t)(row * 320 + 16 * ((j >> 3) ^ ((row >> 1) & 3)) + (j & 7) * 2);
}
__device__ __forceinline__ uint32_t vuoff(int row, int u){
    return (uint32_t)(row * 320 + 16 * (u ^ ((row >> 1) & 3)));
}
__device__ __forceinline__ uint32_t ldsV(uint32_t base, int r0, int ln, int u0){
    int g = ln >> 3;
    int row = r0 + ((g & 1) << 3) + (ln & 7);
    return base + vuoff(row, u0 + (g >> 1));
}
// ILP-4 split-major 12-MMA block
#define MMA_BLK(t00, t01, t10, t11, ah, al, bh, bl) do { \
    mma16816(t00, ah[0], bh[0], bh[2]); \
    mma16816(t01, ah[0], bh[1], bh[3]); \
    mma16816(t10, ah[1], bh[0], bh[2]); \
    mma16816(t11, ah[1], bh[1], bh[3]); \
    mma16816(t00, ah[0], bl[0], bl[2]); \
    mma16816(t01, ah[0], bl[1], bl[3]); \
    mma16816(t10, ah[1], bl[0], bl[2]); \
    mma16816(t11, ah[1], bl[1], bl[3]); \
    mma16816(t00, al[0], bh[0], bh[2]); \
    mma16816(t01, al[0], bh[1], bh[3]); \
    mma16816(t10, al[1], bh[0], bh[2]); \
    mma16816(t11, al[1], bh[1], bh[3]); \
} while(0)

// ---------------- MLP -------------------------------------------------------
__global__ void k_mlp(const float* __restrict__ x,
                      const float* __restrict__ W0, const float* __restrict__ b0,
                      const float* __restrict__ W1, const float* __restrict__ b1,
                      const float* __restrict__ W2, const float* __restrict__ b2)
{
    int row = blockIdx.x, e = blockIdx.y;
    const float* W  = (e == 0) ? W0 : (e == 1) ? W1 : W2;
    const float* bb = (e == 0) ? b0 : (e == 1) ? b1 : b2;
    __shared__ float xs[DIN];
    int tid = threadIdx.x;
    for (int k = tid; k < DIN; k += 160) xs[k] = x[row * DIN + k];
    __syncthreads();
    if (tid < D) {
        float acc = bb[tid];
        #pragma unroll 8
        for (int k = 0; k < DIN; ++k) acc += xs[k] * W[k * D + tid];
        g_emb[e][row][tid] = (acc >= 0.f) ? acc : 0.1f * acc;
    }
}

// ---------------- emb -> split bf16 images ---------------------------------
__global__ void k_embimg()
{
    int idx = blockIdx.x * 256 + threadIdx.x;
    if (idx >= 3 * 256 * 80) return;
    int e = idx / 20480, rem = idx % 20480;
    int row = rem / 80, kp = rem % 80;
    uint32_t h, l;
    split_pack(g_emb[e][row][2*kp], g_emb[e][row][2*kp+1], h, l);
    *(uint32_t*)&g_eh[e][row][2*kp] = h;
    *(uint32_t*)&g_el[e][row][2*kp] = l;
}

// ---------------- T[i][k][j] -> TB[q][(j*160+i)][k] hi/lo -------------------
__global__ void k_timg(const float* __restrict__ T0, const float* __restrict__ T1,
                       const float* __restrict__ T2, const float* __restrict__ T3,
                       const float* __restrict__ T4, const float* __restrict__ T5)
{
    int q = blockIdx.z, i = blockIdx.y, j0 = blockIdx.x * 32;
    const float* T = (q==0)?T0:(q==1)?T1:(q==2)?T2:(q==3)?T3:(q==4)?T4:T5;
    __shared__ float ts[32][152];
    int tid = threadIdx.x;
    for (int t = tid; t < 150 * 32; t += 256) {
        int k = t >> 5, j = t & 31;
        if (j0 + j < D) ts[j][k] = T[(i * D + k) * D + j0 + j];
    }
    __syncthreads();
    for (int t = tid; t < 32 * 75; t += 256) {
        int j = t / 75, kp = t % 75;
        if (j0 + j < D) {
            uint32_t h, l;
            split_pack(ts[j][2*kp], ts[j][2*kp+1], h, l);
            int n = (j0 + j) * Dp + i;
            *(uint32_t*)&g_tbh[q][n][2*kp] = h;
            *(uint32_t*)&g_tbl[q][n][2*kp] = l;
        }
    }
}

// ---------------- stage A: w = Z . TB^T, 4-stage pipeline -------------------
// M=256, N=25600, K=160. Tile 128x128, warp tile 32x64 (4m x 2n warps).
__device__ __forceinline__ void prefA(uint32_t sb, int slot, int k0, int tid,
    const __nv_bfloat16* Zh, const __nv_bfloat16* Zl,
    const __nv_bfloat16* Bh, const __nv_bfloat16* Bl, int m0, int n0)
{
    if (k0 < Dp) {
        #pragma unroll
        for (int t3 = 0; t3 < 4; ++t3) {
            int t = tid + t3 * 256;
            int arr = t >> 8, rr = (t >> 1) & 127, u = t & 1;
            uint32_t dst = sb + slot * 16384 + arr * 4096 + swz(rr, u);
            const __nv_bfloat16* g;
            if (arr == 0)      g = Zh + (size_t)(m0 + rr) * Dp + k0 + u * 8;
            else if (arr == 1) g = Zl + (size_t)(m0 + rr) * Dp + k0 + u * 8;
            else if (arr == 2) g = Bh + (size_t)(n0 + rr) * Dp + k0 + u * 8;
            else               g = Bl + (size_t)(n0 + rr) * Dp + k0 + u * 8;
            cpa16(dst, g);
        }
    }
    CP_COMMIT();
}

__global__ void __launch_bounds__(256, 2) k_stageA()
{
    extern __shared__ __align__(16) unsigned char smA[];    // 4 x 16384
    uint32_t sb = smem_u32(smA);
    int q = blockIdx.z, m0 = blockIdx.y * 128, n0 = blockIdx.x * 128;
    int tid = threadIdx.x, w = tid >> 5, ln = tid & 31;
    int wm = w & 3, wn = w >> 2;
    int zi = c_ZI[q];
    const __nv_bfloat16 *Zh = &g_eh[zi][0][0], *Zl = &g_el[zi][0][0];
    const __nv_bfloat16 *Bh = &g_tbh[q][0][0], *Bl = &g_tbl[q][0][0];

    float acc[2][8][4];
    #pragma unroll
    for (int a = 0; a < 2; ++a)
        #pragma unroll
        for (int b = 0; b < 8; ++b)
            #pragma unroll
            for (int c = 0; c < 4; ++c) acc[a][b][c] = 0.f;

    prefA(sb, 0, 0,  tid, Zh, Zl, Bh, Bl, m0, n0);
    prefA(sb, 1, 16, tid, Zh, Zl, Bh, Bl, m0, n0);
    prefA(sb, 2, 32, tid, Zh, Zl, Bh, Bl, m0, n0);
    for (int ks = 0; ks < 10; ++ks) {
        CP_WAIT2();
        __syncthreads();
        prefA(sb, (ks + 3) & 3, (ks + 3) * 16, tid, Zh, Zl, Bh, Bl, m0, n0);
        uint32_t base = sb + (ks & 3) * 16384;
        uint32_t ah[2][4], al[2][4];
        #pragma unroll
        for (int mt = 0; mt < 2; ++mt) {
            ldsm4(ah[mt], lds_addr(base,        wm * 32 + mt * 16, ln));
            ldsm4(al[mt], lds_addr(base + 4096, wm * 32 + mt * 16, ln));
        }
        #pragma unroll
        for (int p = 0; p < 4; ++p) {
            uint32_t bh[4], bl[4];
            ldsm4(bh, lds_addr(base + 8192,  wn * 64 + p * 16, ln));
            ldsm4(bl, lds_addr(base + 12288, wn * 64 + p * 16, ln));
            MMA_BLK(acc[0][2*p], acc[0][2*p+1], acc[1][2*p], acc[1][2*p+1], ah, al, bh, bl);
        }
    }

    // epilogue: store wB split-bf16 pairs (acc in regs; no barrier needed)
    __nv_bfloat16* WH = &g_wbh[0][0][0][0];
    __nv_bfloat16* WL = &g_wbl[0][0][0][0];
    int yb = 2 * (ln & 3);
    #pragma unroll
    for (int mt = 0; mt < 2; ++mt) {
        int mA = m0 + wm * 32 + mt * 16 + (ln >> 2);
        #pragma unroll
        for (int nt = 0; nt < 8; ++nt) {
            int n = n0 + wn * 64 + nt * 8 + yb;
            size_t off0 = ((size_t)(q * BZ + mA)) * 25600 + n;
            size_t off1 = off0 + (size_t)8 * 25600;
            uint32_t h, l;
            split_pack(acc[mt][nt][0], acc[mt][nt][1], h, l);
            *(uint32_t*)(WH + off0) = h; *(uint32_t*)(WL + off0) = l;
            split_pack(acc[mt][nt][2], acc[mt][nt][3], h, l);
            *(uint32_t*)(WH + off1) = h; *(uint32_t*)(WL + off1) = l;
        }
    }
}

// ---------------- fused B+C per (q,bz) --------------------------------------
// dyn smem: [0,73728) stage bufs (4x18432) -> reused as Y images [0,81920)
//           [81920,163840) v images; epilogue: s-tile staging at [0,66560)
__device__ __forceinline__ void prefB(uint32_t sb, int slot, int k0, int tid,
    const __nv_bfloat16* Xh, const __nv_bfloat16* Xl,
    const __nv_bfloat16* Wh, const __nv_bfloat16* Wl)
{
    if (k0 < Dp) {
        for (int t = tid; t < 1152; t += 256) {
            uint32_t dst; const __nv_bfloat16* g;
            if (t < 512) {
                int img = t >> 8, rr = (t >> 1) & 127, u = t & 1;
                dst = sb + slot * 18432 + img * 4096 + swz(rr, u);
                g = (img ? Xl : Xh) + (size_t)rr * Dp + k0 + u * 8;
            } else {
                int t2 = t - 512;                          // 0..639
                int img = t2 / 320, r2 = t2 - img * 320;   // 2 imgs x 160 rows x 2 units
                int rr = r2 >> 1, u = r2 & 1;
                dst = sb + slot * 18432 + 8192 + img * 5120 + swz(rr, u);
                g = (img ? Wl : Wh) + (size_t)rr * Dp + k0 + u * 8;
            }
            cpa16(dst, g);
        }
    }
    CP_COMMIT();
}

__global__ void __launch_bounds__(256, 1) k_fusedBC(float* __restrict__ out)
{
    extern __shared__ __align__(16) unsigned char dynsm[];
    uint32_t sb = smem_u32(dynsm);
    int q = blockIdx.y, bz = blockIdx.x, b = bz >> 7, z = bz & 127;
    int tid = threadIdx.x, w = tid >> 5, ln = tid & 31;
    int wm = w & 3, wn = w >> 2;

    const __nv_bfloat16 *Xh = &g_eh[c_XI[q]][b*128][0], *Xl = &g_el[c_XI[q]][b*128][0];
    const __nv_bfloat16 *Wh = &g_wbh[q][bz][0][0],      *Wl = &g_wbl[q][bz][0][0];
    const __nv_bfloat16 *Yh = &g_eh[c_YI[q]][b*128][0], *Yl = &g_el[c_YI[q]][b*128][0];

    // ---- stage B (warp tile 32x80; 4-stage pipeline, 1 sync/iter)
    float accB[2][10][4];
    #pragma unroll
    for (int mt = 0; mt < 2; ++mt)
        #pragma unroll
        for (int i = 0; i < 10; ++i)
            #pragma unroll
            for (int c = 0; c < 4; ++c) accB[mt][i][c] = 0.f;

    prefB(sb, 0, 0,  tid, Xh, Xl, Wh, Wl);
    prefB(sb, 1, 16, tid, Xh, Xl, Wh, Wl);
    prefB(sb, 2, 32, tid, Xh, Xl, Wh, Wl);
    for (int ks = 0; ks < 10; ++ks) {
        CP_WAIT2();
        __syncthreads();
        prefB(sb, (ks + 3) & 3, (ks + 3) * 16, tid, Xh, Xl, Wh, Wl);
        uint32_t base = sb + (ks & 3) * 18432;
        uint32_t ah[2][4], al[2][4];
        #pragma unroll
        for (int mt = 0; mt < 2; ++mt) {
            ldsm4(ah[mt], lds_addr(base,        wm * 32 + mt * 16, ln));
            ldsm4(al[mt], lds_addr(base + 4096, wm * 32 + mt * 16, ln));
        }
        #pragma unroll
        for (int p = 0; p < 5; ++p) {
            uint32_t bh[4], bl[4];
            ldsm4(bh, lds_addr(base + 8192,  wn * 80 + p * 16, ln));
            ldsm4(bl, lds_addr(base + 13312, wn * 80 + p * 16, ln));
            MMA_BLK(accB[0][2*p], accB[0][2*p+1], accB[1][2*p], accB[1][2*p+1], ah, al, bh, bl);
        }
    }
    __syncthreads();   // all stage-B reads done; bufs region free for Y images

    // ---- Y prefetch into [0,81920), overlapped with v writes
    for (int t = tid; t < 5120; t += 256) {
        int img = t / 2560, r2 = t % 2560;
        int r = r2 / 20, u = r2 % 20;
        uint32_t dst = sb + img * 40960 + vuoff(r, u);
        const __nv_bfloat16* g = (img ? Yl : Yh) + (size_t)r * Dp + u * 8;
        cpa16(dst, g);
    }
    CP_COMMIT();

    // ---- v -> split-bf16 smem images at [81920,163840)
    #pragma unroll
    for (int mt = 0; mt < 2; ++mt) {
        #pragma unroll
        for (int n8 = 0; n8 < 10; ++n8) {
            int j  = wn * 80 + n8 * 8 + 2 * (ln & 3);
            int x1 = wm * 32 + mt * 16 + (ln >> 2);
            uint32_t h, l;
            split_pack(accB[mt][n8][0], accB[mt][n8][1], h, l);
            *(uint32_t*)(dynsm + 81920  + voff(x1, j)) = h;
            *(uint32_t*)(dynsm + 122880 + voff(x1, j)) = l;
            split_pack(accB[mt][n8][2], accB[mt][n8][3], h, l);
            *(uint32_t*)(dynsm + 81920  + voff(x1 + 8, j)) = h;
            *(uint32_t*)(dynsm + 122880 + voff(x1 + 8, j)) = l;
        }
    }
    CP_WAIT0();
    __syncthreads();

    // ---- stage C (warp tile 32x64; pure ldsm+mma from images, no syncs)
    float accC[2][8][4];
    #pragma unroll
    for (int mt = 0; mt < 2; ++mt)
        #pragma unroll
        for (int i = 0; i < 8; ++i)
            #pragma unroll
            for (int c = 0; c < 4; ++c) accC[mt][i][c] = 0.f;

    #pragma unroll
    for (int kk = 0; kk < 10; ++kk) {
        int u0 = kk * 2;
        uint32_t ah[2][4], al[2][4];
        #pragma unroll
        for (int mt = 0; mt < 2; ++mt) {
            ldsm4(ah[mt], ldsV(sb + 81920,  wm * 32 + mt * 16, ln, u0));
            ldsm4(al[mt], ldsV(sb + 122880, wm * 32 + mt * 16, ln, u0));
        }
        #pragma unroll
        for (int p = 0; p < 4; ++p) {
            uint32_t bh[4], bl[4];
            ldsm4(bh, ldsV(sb,         wn * 64 + p * 16, ln, u0));
            ldsm4(bl, ldsV(sb + 40960, wn * 64 + p * 16, ln, u0));
            MMA_BLK(accC[0][2*p], accC[0][2*p+1], accC[1][2*p], accC[1][2*p+1], ah, al, bh, bl);
        }
    }
    __syncthreads();   // stage-C smem reads done; reuse region for s-tile

    // ---- epilogue: stage s tile, apply triu_sym reading smem, coalesced out
    float* ss = (float*)dynsm;   // [128][130]
    #pragma unroll
    for (int mt = 0; mt < 2; ++mt) {
        int x = wm * 32 + mt * 16 + (ln >> 2);
        #pragma unroll
        for (int nt = 0; nt < 8; ++nt) {
            int y = wn * 64 + nt * 8 + 2 * (ln & 3);
            ss[x * 130 + y]           = accC[mt][nt][0];
            ss[x * 130 + y + 1]       = accC[mt][nt][1];
            ss[(x + 8) * 130 + y]     = accC[mt][nt][2];
            ss[(x + 8) * 130 + y + 1] = accC[mt][nt][3];
        }
    }
    __syncthreads();

    bool dosym = (q != 0);
    float* o;
    if (q < 4) o = out + (size_t)q * 4194304 + (size_t)bz * 16384;
    else       o = &g_cp[(q - 4) * 2 + b][z][0][0];
    int c0 = ln * 4;
    #pragma unroll
    for (int rr = 0; rr < 16; ++rr) {
        int r = w * 16 + rr;
        const float* pr = ss + r * 130;
        float4 v;
        v.x = (!dosym || r <= c0    ) ? pr[c0]     : ss[(c0)     * 130 + r];
        v.y = (!dosym || r <= c0 + 1) ? pr[c0 + 1] : ss[(c0 + 1) * 130 + r];
        v.z = (!dosym || r <= c0 + 2) ? pr[c0 + 2] : ss[(c0 + 2) * 130 + r];
        v.w = (!dosym || r <= c0 + 3) ? pr[c0 + 3] : ss[(c0 + 3) * 130 + r];
        *(float4*)(o + (size_t)r * 128 + c0) = v;
    }
}

// ---------------- co-parent permute: g_cp[t*2+b][z][x][y] -> out[b][x][y][z]
__global__ void k_cop(float* __restrict__ out)
{
    __shared__ float ts[32][33];
    int tile = blockIdx.x;           // 0..15: zt = tile>>2, yt = tile&3
    int x    = blockIdx.y;           // 0..127
    int tb   = blockIdx.z;           // 0..3: t = tb>>1, b = tb&1
    int z0 = (tile >> 2) * 32, y0 = (tile & 3) * 32;
    int tx = threadIdx.x, ty = threadIdx.y;    // 32 x 8
    const float* src = &g_cp[tb][0][x][0];
    #pragma unroll
    for (int i = ty; i < 32; i += 8)
        ts[i][tx] = src[(size_t)(z0 + i) * 16384 + y0 + tx];
    __syncthreads();
    float* dst = out + (size_t)(4 + (tb >> 1)) * 4194304 + (size_t)(tb & 1) * 2097152
               + (size_t)x * 16384;
    #pragma unroll
    for (int i = ty; i < 32; i += 8)
        dst[(size_t)(y0 + i) * 128 + z0 + tx] = ts[tx][i];
}

// ---------------------------------------------------------------------------
extern "C" void kernel_launch(void* const* d_in, const int* in_sizes, int n_in,
                              void* d_out, int out_size)
{
    const float* x      = (const float*)d_in[0];
    const float* W_sh   = (const float*)d_in[1];
    const float* b_sh   = (const float*)d_in[2];
    const float* W_st   = (const float*)d_in[3];
    const float* b_st   = (const float*)d_in[4];
    const float* W_p    = (const float*)d_in[5];
    const float* b_p    = (const float*)d_in[6];
    const float* T_pt   = (const float*)d_in[7];
    const float* T_ph   = (const float*)d_in[8];
    const float* T_phsib= (const float*)d_in[9];
    const float* T_ptsib= (const float*)d_in[10];
    const float* T_phcop= (const float*)d_in[11];
    const float* T_ptcop= (const float*)d_in[12];

    static bool attr_done = false;
    if (!attr_done) {
        cudaFuncSetAttribute(k_stageA,  cudaFuncAttributeMaxDynamicSharedMemorySize, 65536);
        cudaFuncSetAttribute(k_fusedBC, cudaFuncAttributeMaxDynamicSharedMemorySize, 163840);
        attr_done = true;
    }

    k_mlp   <<<dim3(BZ, 3), 160>>>(x, W_sh, b_sh, W_st, b_st, W_p, b_p);
    k_embimg<<<240, 256>>>();
    // q order: 0=T_ph 1=T_pt 2=T_phsib 3=T_ptsib 4=T_phcop 5=T_ptcop
    k_timg  <<<dim3(5, D, 6), 256>>>(T_ph, T_pt, T_phsib, T_ptsib, T_phcop, T_ptcop);
    k_stageA<<<dim3(200, 2, 6), 256, 65536>>>();
    k_fusedBC<<<dim3(BZ, 6), 256, 163840>>>((float*)d_out);
    k_cop   <<<dim3(16, 128, 4), dim3(32, 8)>>>((float*)d_out);
}